// round 10
// baseline (speedup 1.0000x reference)
#include <cuda_runtime.h>
#include <math.h>

#define NF 101
#define UNITS 125
#define G3 375
#define OUT 202
#define KSZ (UNITS*OUT)
#define NW (KSZ+OUT)
#define TT 70
#define STEPS1 56
#define GAMMA 28
#define BATCH 4096
#define CCONST 0.54132485f

// fused K layout: v = [x(112 pad) | h(128 pad)], weights row-fused the same way
#define KX 112
#define KV 240
#define WROW 384          // 3 gates * 128 padded units (floats) per k-row
#define DROW 256          // padded dense output row (floats)

#define OFF_GW 0
#define SZ_GW (KV*WROW)
#define OFF_B0 (OFF_GW+SZ_GW)
#define OFF_B1 (OFF_B0+WROW)
#define OFF_KP (OFF_B1+WROW)
#define SZ_KP (GAMMA*128*DROW)
#define OFF_BIAS (OFF_KP+SZ_KP)
#define SZ_BIAS (GAMMA*DROW)
#define SCRATCH_TOTAL (OFF_BIAS+SZ_BIAS)

__device__ __align__(16) float g_scratch[SCRATCH_TOTAL];

typedef unsigned long long u64;

// ---- packed f32x2 helpers (sm_103a) ----
__device__ __forceinline__ void fma2(u64& d, u64 a, u64 b){
    asm("fma.rn.f32x2 %0, %1, %2, %0;" : "+l"(d) : "l"(a), "l"(b));
}
__device__ __forceinline__ u64 pack2(float x, float y){
    u64 r; asm("mov.b64 %0, {%1,%2};" : "=l"(r) : "f"(x), "f"(y)); return r;
}
__device__ __forceinline__ float2 unpack2(u64 v){
    float2 r; asm("mov.b64 {%0,%1}, %2;" : "=f"(r.x), "=f"(r.y) : "l"(v)); return r;
}
// 16B global load, L2-resident hint (.cg): weights are shared by all CTAs
__device__ __forceinline__ ulonglong2 ldg2(const u64* p){
    ulonglong2 v;
    asm("ld.global.cg.v2.u64 {%0,%1}, [%2];" : "=l"(v.x), "=l"(v.y) : "l"(p));
    return v;
}

// ---- math ----
__device__ __forceinline__ float sp(float x){
    float r = log1pf(__expf(x));
    return (x > 15.f) ? x : r;
}
__device__ __forceinline__ float sigm(float x){
    return __fdividef(1.f, 1.f + __expf(-x));
}
__device__ __forceinline__ float mytanh(float x){
    return __fdividef(2.f, 1.f + __expf(-2.f*x)) - 1.f;
}

// ---- weight prep ----
__device__ __forceinline__ float dvw(int s, int w,
    const float* dv_loc, const float* dv_rho, const float* eps_w0, const float* eps_w)
{
    float sd = 1e-5f + 0.01f * sp(CCONST + dv_rho[w]);
    float e  = (s == 0) ? eps_w0[w] : eps_w[(size_t)(s-1)*NW + w];
    return dv_loc[w] + sd * e;
}

__global__ void prep_kernel(const float* __restrict__ W_k, const float* __restrict__ U,
                            const float* __restrict__ b,   const float* __restrict__ dv_loc,
                            const float* __restrict__ dv_rho, const float* __restrict__ eps_w0,
                            const float* __restrict__ eps_w)
{
    for (int i = blockIdx.x*blockDim.x + threadIdx.x; i < SCRATCH_TOTAL; i += gridDim.x*blockDim.x){
        float v = 0.f;
        if (i < OFF_B0){
            int k = i / WROW, c = i % WROW;
            int g = c / 128, u = c % 128;
            if (u < UNITS){
                if (k < NF)                       v = W_k[k*G3 + g*UNITS + u];
                else if (k >= KX && k < KX+UNITS) v = U[(k-KX)*G3 + g*UNITS + u];
            }
        } else if (i < OFF_B1){
            // B0: z,r gates get combined bias (b0+b1); h gate gets b0 only
            int c = i - OFF_B0; int g = c / 128, u = c % 128;
            if (u < UNITS) v = (g < 2) ? (b[g*UNITS + u] + b[G3 + g*UNITS + u])
                                       : b[2*UNITS + u];
        } else if (i < OFF_KP){
            // B1: only h gate slot used (b1_h)
            int c = i - OFF_B1; int g = c / 128, u = c % 128;
            if (u < UNITS && g == 2) v = b[G3 + 2*UNITS + u];
        } else if (i < OFF_BIAS){
            int idx = i - OFF_KP; int s = idx / (128*DROW);
            int rem = idx % (128*DROW); int u = rem / DROW, o = rem % DROW;
            if (u < UNITS && o < OUT) v = dvw(s, u*OUT + o, dv_loc, dv_rho, eps_w0, eps_w);
        } else {
            int idx = i - OFF_BIAS; int s = idx / DROW, o = idx % DROW;
            if (o < OUT) v = dvw(s, KSZ + o, dv_loc, dv_rho, eps_w0, eps_w);
        }
        g_scratch[i] = v;
    }
}

// ---- main kernel geometry ----
#define RC 16             // batch rows per CTA
#define VTS 18            // u64 stride of one k-row of vT (16 rows + 2 pad; even for LDS.128)
#define YS 208            // float stride per row of y

#define SMEM_VT_BYTES (KV*VTS*8)        // 34560
#define SMEM_Y_BYTES  (RC*YS*4)         // 13312
#define SMEM_BYTES (SMEM_VT_BYTES + SMEM_Y_BYTES)

// Thread layout (both GEMVs):
//   pc = warp*4 + (lane&3)  : column group, pc in [0,32)
//   rg = lane>>2            : row group, rg in [0,8) ; rows 2*rg, 2*rg+1
// GRU: thread owns gate u64-cols {2pc, 2pc+1} for all 3 gates (units 4pc..4pc+3)
// Dense: thread owns u64-cols {4pc..4pc+3} (floats 8pc..8pc+7)

__device__ __forceinline__ void gru_step(u64* __restrict__ vT, int pc, int r0)
{
    u64 az[2][2], ar[2][2], ahx[2][2], ahh[2][2];   // [col][row]
    {
        const u64* B0 = (const u64*)(g_scratch + OFF_B0);
        const u64* B1 = (const u64*)(g_scratch + OFF_B1);
        #pragma unroll
        for (int c2 = 0; c2 < 2; ++c2){
            int col = 2*pc + c2;
            u64 bz = B0[col], br = B0[64 + col], bhx = B0[128 + col], bhh = B1[128 + col];
            #pragma unroll
            for (int r = 0; r < 2; ++r){ az[c2][r]=bz; ar[c2][r]=br; ahx[c2][r]=bhx; ahh[c2][r]=bhh; }
        }
    }
    const u64* wb = (const u64*)(g_scratch + OFF_GW) + 2*pc;

    // phase A: k in [0,112) -> z, r, h_x
    #pragma unroll 4
    for (int k = 0; k < KX; ++k){
        ulonglong2 o = *(const ulonglong2*)(vT + k*VTS + r0);
        const u64* wk = wb + k*192;
        ulonglong2 wz = ldg2(wk);
        ulonglong2 wr = ldg2(wk + 64);
        ulonglong2 wh = ldg2(wk + 128);
        fma2(az[0][0], wz.x, o.x);  fma2(az[0][1], wz.x, o.y);
        fma2(az[1][0], wz.y, o.x);  fma2(az[1][1], wz.y, o.y);
        fma2(ar[0][0], wr.x, o.x);  fma2(ar[0][1], wr.x, o.y);
        fma2(ar[1][0], wr.y, o.x);  fma2(ar[1][1], wr.y, o.y);
        fma2(ahx[0][0], wh.x, o.x); fma2(ahx[0][1], wh.x, o.y);
        fma2(ahx[1][0], wh.y, o.x); fma2(ahx[1][1], wh.y, o.y);
    }
    // phase B: k in [112,240) -> z, r, h_h
    #pragma unroll 4
    for (int k = KX; k < KV; ++k){
        ulonglong2 o = *(const ulonglong2*)(vT + k*VTS + r0);
        const u64* wk = wb + k*192;
        ulonglong2 wz = ldg2(wk);
        ulonglong2 wr = ldg2(wk + 64);
        ulonglong2 wh = ldg2(wk + 128);
        fma2(az[0][0], wz.x, o.x);  fma2(az[0][1], wz.x, o.y);
        fma2(az[1][0], wz.y, o.x);  fma2(az[1][1], wz.y, o.y);
        fma2(ar[0][0], wr.x, o.x);  fma2(ar[0][1], wr.x, o.y);
        fma2(ar[1][0], wr.y, o.x);  fma2(ar[1][1], wr.y, o.y);
        fma2(ahh[0][0], wh.x, o.x); fma2(ahh[0][1], wh.x, o.y);
        fma2(ahh[1][0], wh.y, o.x); fma2(ahh[1][1], wh.y, o.y);
    }
    __syncthreads();   // everyone done reading old h
    // nonlinearity + h update: units 4pc..4pc+3, rows r0..r0+1 (same thread owns read+write)
    #pragma unroll
    for (int c2 = 0; c2 < 2; ++c2){
        int u0 = 2*(2*pc + c2);           // first unit of this u64 col
        #pragma unroll
        for (int r = 0; r < 2; ++r){
            float2 vz  = unpack2(az[c2][r]);
            float2 vr  = unpack2(ar[c2][r]);
            float2 vhx = unpack2(ahx[c2][r]);
            float2 vhh = unpack2(ahh[c2][r]);
            int row = r0 + r;
            u64* h0p = vT + (KX + u0    )*VTS + row;
            u64* h1p = vT + (KX + u0 + 1)*VTS + row;
            float hold0 = unpack2(*h0p).x;
            float hold1 = unpack2(*h1p).x;
            float z0 = sigm(vz.x), z1 = sigm(vz.y);
            float g0 = sigm(vr.x), g1 = sigm(vr.y);
            float c0 = mytanh(vhx.x + g0*vhh.x);
            float c1 = mytanh(vhx.y + g1*vhh.y);
            float h0 = z0*hold0 + (1.f - z0)*c0;
            float h1 = z1*hold1 + (1.f - z1)*c1;
            *h0p = pack2(h0, h0);
            *h1p = pack2(h1, h1);
        }
    }
    __syncthreads();   // h_new visible
}

__device__ __forceinline__ void dense_step(int s, const u64* __restrict__ vT,
                                           float* __restrict__ sh_y, int pc, int r0)
{
    u64 acc[4][2];     // [u64 col j][row]
    {
        const u64* bias = (const u64*)(g_scratch + OFF_BIAS) + s*128 + 4*pc;
        #pragma unroll
        for (int j = 0; j < 4; ++j){
            u64 bv = bias[j];
            acc[j][0] = bv; acc[j][1] = bv;
        }
    }
    const u64* kb = (const u64*)(g_scratch + OFF_KP) + (size_t)s*(128*128) + 4*pc;
    #pragma unroll 4
    for (int k = 0; k < 128; ++k){
        ulonglong2 o = *(const ulonglong2*)(vT + (KX + k)*VTS + r0);
        const u64* kk = kb + k*128;
        ulonglong2 w01 = ldg2(kk);
        ulonglong2 w23 = ldg2(kk + 2);
        fma2(acc[0][0], w01.x, o.x); fma2(acc[0][1], w01.x, o.y);
        fma2(acc[1][0], w01.y, o.x); fma2(acc[1][1], w01.y, o.y);
        fma2(acc[2][0], w23.x, o.x); fma2(acc[2][1], w23.x, o.y);
        fma2(acc[3][0], w23.y, o.x); fma2(acc[3][1], w23.y, o.y);
    }
    #pragma unroll
    for (int j = 0; j < 4; ++j){
        int o = 8*pc + 2*j;
        #pragma unroll
        for (int r = 0; r < 2; ++r){
            float2 v = unpack2(acc[j][r]);
            float* yr = sh_y + (size_t)(r0 + r)*YS;
            if (o     < OUT) yr[o]     = v.x;
            if (o + 1 < OUT) yr[o + 1] = v.y;
        }
    }
    __syncthreads();
}

__global__ void __launch_bounds__(256, 2)
rnn_kernel(const float* __restrict__ inputs, const float* __restrict__ eps_s,
           float* __restrict__ out)
{
    extern __shared__ unsigned char smem[];
    u64*   vT   = (u64*)smem;                       // [KV][VTS] u64, transposed operand
    float* sh_y = (float*)(smem + SMEM_VT_BYTES);   // [RC][YS]

    const int tid  = threadIdx.x;
    const int lane = tid & 31;
    const int warp = tid >> 5;
    const int pc   = warp*4 + (lane & 3);   // 0..31
    const int r0   = (lane >> 2) * 2;       // 0,2,..,14
    const int row0 = blockIdx.x * RC;

    // zero vT (x pad, h init, all pad stays 0)
    for (int i = tid; i < KV*VTS; i += 256) vT[i] = 0ULL;
    __syncthreads();

    // phase 1: teacher-forced GRU (56 steps)
    for (int t = 0; t < STEPS1; ++t){
        for (int i = tid; i < RC*NF; i += 256){
            int r = i / NF, k = i - r*NF;
            float v = inputs[((size_t)(row0 + r)*TT + t)*NF + k];
            vT[k*VTS + r] = pack2(v, v);
        }
        __syncthreads();
        gru_step(vT, pc, r0);
    }

    // y0 + feedback loop
    for (int s = 0; s < GAMMA; ++s){
        if (s > 0){
            for (int i = tid; i < RC*NF; i += 256){
                int r = i / NF, k = i - r*NF;
                float loc = sh_y[r*YS + k];
                float sc  = 1e-5f + 0.05f*sp(CCONST + sh_y[r*YS + NF + k]);
                float xv  = loc + sc * eps_s[((size_t)(s-1)*BATCH + row0 + r)*NF + k];
                vT[k*VTS + r] = pack2(xv, xv);
            }
            __syncthreads();
            gru_step(vT, pc, r0);
        }
        dense_step(s, vT, sh_y, pc, r0);
        // emit: loc passthrough, scale transform
        for (int i = tid; i < RC*OUT; i += 256){
            int r = i / OUT, o = i - r*OUT;
            float v = sh_y[r*YS + o];
            if (o >= NF) v = 1e-5f + 0.05f*sp(CCONST + v);
            out[((size_t)(row0 + r)*GAMMA + s)*OUT + o] = v;
        }
    }
}

extern "C" void kernel_launch(void* const* d_in, const int* in_sizes, int n_in,
                              void* d_out, int out_size)
{
    const float* inputs = (const float*)d_in[0];
    const float* W_k    = (const float*)d_in[1];
    const float* U      = (const float*)d_in[2];
    const float* b      = (const float*)d_in[3];
    const float* dv_loc = (const float*)d_in[4];
    const float* dv_rho = (const float*)d_in[5];
    const float* eps_w0 = (const float*)d_in[6];
    const float* eps_w  = (const float*)d_in[7];
    const float* eps_s  = (const float*)d_in[8];
    float* out = (float*)d_out;

    (void)in_sizes; (void)n_in; (void)out_size;

    cudaFuncSetAttribute(rnn_kernel, cudaFuncAttributeMaxDynamicSharedMemorySize, SMEM_BYTES);

    prep_kernel<<<1024, 256>>>(W_k, U, b, dv_loc, dv_rho, eps_w0, eps_w);
    rnn_kernel<<<BATCH/RC, 256, SMEM_BYTES>>>(inputs, eps_s, out);
}

// round 12
// speedup vs baseline: 1.1479x; 1.1479x over previous
#include <cuda_runtime.h>
#include <math.h>

#define NF 101
#define UNITS 125
#define G3 375
#define OUT 202
#define KSZ (UNITS*OUT)
#define NW (KSZ+OUT)
#define TT 70
#define STEPS1 56
#define GAMMA 28
#define BATCH 4096
#define CCONST 0.54132485f

#define GCOL 384          // 3 gates * 128 padded units
#define DCOL 256          // padded dense output row

// g_scratch offsets (floats)
#define OFF_WX 0
#define SZ_WX (NF*GCOL)             // 38784
#define OFF_UU (OFF_WX+SZ_WX)
#define SZ_UU (UNITS*GCOL)          // 48000
#define OFF_BC (OFF_UU+SZ_UU)       // 384 combined biases (z,r: b0+b1; h: b0h)
#define OFF_B1H (OFF_BC+GCOL)       // 128 (b1h)
#define OFF_KP (OFF_B1H+128)
#define SZ_KP (GAMMA*UNITS*DCOL)    // 896000
#define OFF_DB (OFF_KP+SZ_KP)
#define SZ_DB (GAMMA*DCOL)
#define SCRATCH_TOTAL (OFF_DB+SZ_DB)

__device__ __align__(16) float g_scratch[SCRATCH_TOTAL];
__device__ __align__(16) float g_y[BATCH*OUT];      // raw dense outputs (feedback source)

typedef unsigned long long u64;

// ---- packed f32x2 helpers ----
__device__ __forceinline__ void fma2(u64& d, u64 a, u64 b){
    asm("fma.rn.f32x2 %0, %1, %2, %0;" : "+l"(d) : "l"(a), "l"(b));
}
__device__ __forceinline__ u64 pack2(float x, float y){
    u64 r; asm("mov.b64 %0, {%1,%2};" : "=l"(r) : "f"(x), "f"(y)); return r;
}
__device__ __forceinline__ float2 unpack2(u64 v){
    float2 r; asm("mov.b64 {%0,%1}, %2;" : "=f"(r.x), "=f"(r.y) : "l"(v)); return r;
}
__device__ __forceinline__ ulonglong2 ldg2(const u64* p){   // 16B L2-resident load
    ulonglong2 v;
    asm("ld.global.cg.v2.u64 {%0,%1}, [%2];" : "=l"(v.x), "=l"(v.y) : "l"(p));
    return v;
}

// ---- math ----
__device__ __forceinline__ float sp(float x){
    float r = log1pf(__expf(x));
    return (x > 15.f) ? x : r;
}
__device__ __forceinline__ float sigm(float x){ return __fdividef(1.f, 1.f + __expf(-x)); }
__device__ __forceinline__ float mytanh(float x){ return __fdividef(2.f, 1.f + __expf(-2.f*x)) - 1.f; }

// ---- weight prep ----
__device__ __forceinline__ float dvw(int s, int w,
    const float* dv_loc, const float* dv_rho, const float* eps_w0, const float* eps_w)
{
    float sd = 1e-5f + 0.01f * sp(CCONST + dv_rho[w]);
    float e  = (s == 0) ? eps_w0[w] : eps_w[(size_t)(s-1)*NW + w];
    return dv_loc[w] + sd * e;
}

__global__ void prep_kernel(const float* __restrict__ W_k, const float* __restrict__ U,
                            const float* __restrict__ b,   const float* __restrict__ dv_loc,
                            const float* __restrict__ dv_rho, const float* __restrict__ eps_w0,
                            const float* __restrict__ eps_w)
{
    for (int i = blockIdx.x*blockDim.x + threadIdx.x; i < SCRATCH_TOTAL; i += gridDim.x*blockDim.x){
        float v = 0.f;
        if (i < OFF_UU){
            int k = i / GCOL, c = i % GCOL;
            int g = c / 128, u = c % 128;
            if (u < UNITS) v = W_k[k*G3 + g*UNITS + u];
        } else if (i < OFF_BC){
            int idx = i - OFF_UU; int k = idx / GCOL, c = idx % GCOL;
            int g = c / 128, u = c % 128;
            if (u < UNITS) v = U[k*G3 + g*UNITS + u];
        } else if (i < OFF_B1H){
            int c = i - OFF_BC; int g = c / 128, u = c % 128;
            if (u < UNITS) v = (g < 2) ? (b[g*UNITS + u] + b[G3 + g*UNITS + u])
                                       : b[2*UNITS + u];
        } else if (i < OFF_KP){
            int u = i - OFF_B1H;
            if (u < UNITS) v = b[G3 + 2*UNITS + u];
        } else if (i < OFF_DB){
            int idx = i - OFF_KP; int s = idx / (UNITS*DCOL);
            int rem = idx % (UNITS*DCOL); int k = rem / DCOL, o = rem % DCOL;
            if (o < OUT) v = dvw(s, k*OUT + o, dv_loc, dv_rho, eps_w0, eps_w);
        } else {
            int idx = i - OFF_DB; int s = idx / DCOL, o = idx % DCOL;
            if (o < OUT) v = dvw(s, KSZ + o, dv_loc, dv_rho, eps_w0, eps_w);
        }
        g_scratch[i] = v;
    }
}

// ---- main kernel: one 512-thread CTA per SM, RC=32 rows ----
#define RC 32
#define RS 34             // f32 row stride of transposed operands (even)

#define SMEM_U_BYTES  (UNITS*GCOL*4)     // 192000
#define SMEM_H_BYTES  (128*RS*4)         // 17408  (128 unit rows incl pad)
#define SMEM_X_BYTES  (NF*RS*4)          // 13736
#define SMEM_BYTES (SMEM_U_BYTES + SMEM_H_BYTES + SMEM_X_BYTES)   // 223144

// thread map: pc = warp*2 + (lane&1) in [0,32): owns u64 gate-cols {2pc,2pc+1} (units 4pc..4pc+3)
//             rg = lane>>1 in [0,16): rows {2rg, 2rg+1}
__device__ __forceinline__ void gru_step(const float* __restrict__ smU,
                                         float* __restrict__ svh,
                                         const float* __restrict__ sxT,
                                         int pc, int rg)
{
    u64 az[2][2], ar[2][2], ahx[2][2], ahh[2][2];   // [c2][row]
    {
        const u64* BC  = (const u64*)(g_scratch + OFF_BC);
        const u64* B1H = (const u64*)(g_scratch + OFF_B1H);
        #pragma unroll
        for (int c2 = 0; c2 < 2; ++c2){
            u64 bz = BC[2*pc + c2], br = BC[64 + 2*pc + c2];
            u64 bx = BC[128 + 2*pc + c2], bh = B1H[2*pc + c2];
            #pragma unroll
            for (int r = 0; r < 2; ++r){ az[c2][r]=bz; ar[c2][r]=br; ahx[c2][r]=bx; ahh[c2][r]=bh; }
        }
    }
    // x-part: k in [0,101), weights streamed from L2
    {
        const u64* wb = (const u64*)(g_scratch + OFF_WX) + 2*pc;
        const float* xb = sxT + 2*rg;
        #pragma unroll 4
        for (int k = 0; k < NF; ++k){
            float2 xf = *(const float2*)(xb + k*RS);
            u64 o0 = pack2(xf.x, xf.x), o1 = pack2(xf.y, xf.y);
            const u64* wk = wb + k*192;
            ulonglong2 wz = ldg2(wk);
            ulonglong2 wr = ldg2(wk + 64);
            ulonglong2 wh = ldg2(wk + 128);
            fma2(az[0][0], wz.x, o0);  fma2(az[0][1], wz.x, o1);
            fma2(az[1][0], wz.y, o0);  fma2(az[1][1], wz.y, o1);
            fma2(ar[0][0], wr.x, o0);  fma2(ar[0][1], wr.x, o1);
            fma2(ar[1][0], wr.y, o0);  fma2(ar[1][1], wr.y, o1);
            fma2(ahx[0][0], wh.x, o0); fma2(ahx[0][1], wh.x, o1);
            fma2(ahx[1][0], wh.y, o0); fma2(ahx[1][1], wh.y, o1);
        }
    }
    // h-part: k in [0,125), weights from SMEM
    {
        const float* hb = svh + 2*rg;
        #pragma unroll 4
        for (int k = 0; k < UNITS; ++k){
            float2 hf = *(const float2*)(hb + k*RS);
            u64 o0 = pack2(hf.x, hf.x), o1 = pack2(hf.y, hf.y);
            ulonglong2 wz = *(const ulonglong2*)((const u64*)smU + k*192 + 2*pc);
            ulonglong2 wr = *(const ulonglong2*)((const u64*)smU + k*192 + 64 + 2*pc);
            ulonglong2 wh = *(const ulonglong2*)((const u64*)smU + k*192 + 128 + 2*pc);
            fma2(az[0][0], wz.x, o0);  fma2(az[0][1], wz.x, o1);
            fma2(az[1][0], wz.y, o0);  fma2(az[1][1], wz.y, o1);
            fma2(ar[0][0], wr.x, o0);  fma2(ar[0][1], wr.x, o1);
            fma2(ar[1][0], wr.y, o0);  fma2(ar[1][1], wr.y, o1);
            fma2(ahh[0][0], wh.x, o0); fma2(ahh[0][1], wh.x, o1);
            fma2(ahh[1][0], wh.y, o0); fma2(ahh[1][1], wh.y, o1);
        }
    }
    __syncthreads();   // all reads of old h complete
    #pragma unroll
    for (int c2 = 0; c2 < 2; ++c2){
        int u0 = 4*pc + 2*c2;
        #pragma unroll
        for (int r = 0; r < 2; ++r){
            int row = 2*rg + r;
            float2 vz = unpack2(az[c2][r]);
            float2 vr = unpack2(ar[c2][r]);
            float2 vx = unpack2(ahx[c2][r]);
            float2 vh = unpack2(ahh[c2][r]);
            float hold0 = svh[u0*RS + row];
            float hold1 = svh[(u0+1)*RS + row];
            float z0 = sigm(vz.x), z1 = sigm(vz.y);
            float g0 = sigm(vr.x), g1 = sigm(vr.y);
            float c0 = mytanh(vx.x + g0*vh.x);
            float c1 = mytanh(vx.y + g1*vh.y);
            svh[u0*RS + row]     = z0*hold0 + (1.f - z0)*c0;
            svh[(u0+1)*RS + row] = z1*hold1 + (1.f - z1)*c1;
        }
    }
    __syncthreads();   // new h visible
}

__device__ __forceinline__ void dense_step(int s, const float* __restrict__ svh,
                                           float* __restrict__ out, int row0,
                                           int pd, int rg)
{
    u64 acc[4][2];
    {
        const u64* db = (const u64*)(g_scratch + OFF_DB) + s*128 + 4*pd;
        #pragma unroll
        for (int j = 0; j < 4; ++j){ acc[j][0] = db[j]; acc[j][1] = db[j]; }
    }
    const u64* kp = (const u64*)(g_scratch + OFF_KP) + (size_t)s*(UNITS*128) + 4*pd;
    const float* hb = svh + 2*rg;
    #pragma unroll 4
    for (int k = 0; k < UNITS; ++k){
        float2 hf = *(const float2*)(hb + k*RS);
        u64 o0 = pack2(hf.x, hf.x), o1 = pack2(hf.y, hf.y);
        ulonglong2 w01 = ldg2(kp + k*128);
        ulonglong2 w23 = ldg2(kp + k*128 + 2);
        fma2(acc[0][0], w01.x, o0); fma2(acc[0][1], w01.x, o1);
        fma2(acc[1][0], w01.y, o0); fma2(acc[1][1], w01.y, o1);
        fma2(acc[2][0], w23.x, o0); fma2(acc[2][1], w23.x, o1);
        fma2(acc[3][0], w23.y, o0); fma2(acc[3][1], w23.y, o1);
    }
    #pragma unroll
    for (int j = 0; j < 4; ++j){
        int of = 8*pd + 2*j;
        if (of < OUT){
            #pragma unroll
            for (int r = 0; r < 2; ++r){
                int row = row0 + 2*rg + r;
                float2 v = unpack2(acc[j][r]);
                // raw y for feedback
                g_y[(size_t)row*OUT + of]     = v.x;
                g_y[(size_t)row*OUT + of + 1] = v.y;
                // transformed output
                float t0 = (of     >= NF) ? (1e-5f + 0.05f*sp(CCONST + v.x)) : v.x;
                float t1 = (of + 1 >= NF) ? (1e-5f + 0.05f*sp(CCONST + v.y)) : v.y;
                float* op = out + ((size_t)row*GAMMA + s)*OUT;
                op[of]     = t0;
                op[of + 1] = t1;
            }
        }
    }
    __syncthreads();   // g_y visible to next feedback build
}

__global__ void __launch_bounds__(512, 1)
rnn_kernel(const float* __restrict__ inputs, const float* __restrict__ eps_s,
           float* __restrict__ out)
{
    extern __shared__ unsigned char smem[];
    float* smU = (float*)smem;                                  // [125][384]
    float* svh = (float*)(smem + SMEM_U_BYTES);                 // [128][RS]
    float* sxT = (float*)(smem + SMEM_U_BYTES + SMEM_H_BYTES);  // [101][RS]

    const int tid  = threadIdx.x;
    const int lane = tid & 31;
    const int warp = tid >> 5;
    const int pc   = warp*2 + (lane & 1);    // 0..31
    const int rg   = lane >> 1;              // 0..15
    const int row0 = blockIdx.x * RC;

    // load U into smem; zero h
    for (int i = tid; i < UNITS*GCOL; i += 512) smU[i] = g_scratch[OFF_UU + i];
    for (int i = tid; i < 128*RS; i += 512) svh[i] = 0.f;
    __syncthreads();

    // phase 1: teacher-forced GRU (56 steps)
    for (int t = 0; t < STEPS1; ++t){
        for (int i = tid; i < RC*NF; i += 512){
            int r = i / NF, k = i - r*NF;
            sxT[k*RS + r] = inputs[((size_t)(row0 + r)*TT + t)*NF + k];
        }
        __syncthreads();
        gru_step(smU, svh, sxT, pc, rg);
    }

    // y0 + feedback loop
    for (int s = 0; s < GAMMA; ++s){
        if (s > 0){
            for (int i = tid; i < RC*NF; i += 512){
                int r = i / NF, k = i - r*NF;
                int row = row0 + r;
                float loc = g_y[(size_t)row*OUT + k];
                float sc  = 1e-5f + 0.05f*sp(CCONST + g_y[(size_t)row*OUT + NF + k]);
                sxT[k*RS + r] = loc + sc * eps_s[((size_t)(s-1)*BATCH + row)*NF + k];
            }
            __syncthreads();
            gru_step(smU, svh, sxT, pc, rg);
        }
        dense_step(s, svh, out, row0, pc, rg);
    }
}

extern "C" void kernel_launch(void* const* d_in, const int* in_sizes, int n_in,
                              void* d_out, int out_size)
{
    const float* inputs = (const float*)d_in[0];
    const float* W_k    = (const float*)d_in[1];
    const float* U      = (const float*)d_in[2];
    const float* b      = (const float*)d_in[3];
    const float* dv_loc = (const float*)d_in[4];
    const float* dv_rho = (const float*)d_in[5];
    const float* eps_w0 = (const float*)d_in[6];
    const float* eps_w  = (const float*)d_in[7];
    const float* eps_s  = (const float*)d_in[8];
    float* out = (float*)d_out;

    (void)in_sizes; (void)n_in; (void)out_size;

    cudaFuncSetAttribute(rnn_kernel, cudaFuncAttributeMaxDynamicSharedMemorySize, SMEM_BYTES);

    prep_kernel<<<1024, 256>>>(W_k, U, b, dv_loc, dv_rho, eps_w0, eps_w);
    rnn_kernel<<<BATCH/RC, 512, SMEM_BYTES>>>(inputs, eps_s, out);
}